// round 2
// baseline (speedup 1.0000x reference)
#include <cuda_runtime.h>

// RoPE: X (L=2048, D=4096, N=4) fp32 -> out same shape.
// out[:, :half] = cos*x1 - sin*x2 ; out[:, half:] = sin*x1 + cos*x2
// ang[l, d] = (l+1) * 10000^(d/2048), angles up to ~2.05e7.
//
// Bit-critical path (must match XLA:CPU / glibc correctly-rounded fp32):
//   theta: computed in double via exp2, error ~2e-15 rel -> rounds to the
//          same fp32 as glibc's correctly-rounded powf.
//   ang:   single fp32 multiply (__fmul_rn) of exact operands.
// Tolerance-tolerant path (threshold 1e-3): sin/cos of the fp32 ang, via
// double Cody-Waite reduction (residual ~1e-16) + fp32 polynomials.

constexpr int L    = 2048;
constexpr int D    = 4096;   // feature dim, indexed in float4 units over N=4
constexpr int HALF = 2048;
constexpr int LPER = 8;      // l-rows per thread (amortizes theta)
constexpr int TPB  = 256;

__device__ __forceinline__ void sincos_of_f32(float ang, float& s_out, float& c_out)
{
    // ang in [1, 2.05e7], exactly representable in double.
    const double ad = (double)ang;
    const double kd = rint(ad * 0.63661977236758134308);      // 2/pi
    double rd = fma(-kd, 1.57079632679489661923, ad);          // pi/2 hi (exact fma)
    rd        = fma(-kd, 6.12323399573676603587e-17, rd);      // pi/2 lo
    const float r = (float)rd;                                 // |r| <= pi/4, err ~1e-16
    const int   q = ((int)kd) & 3;

    const float t = r * r;
    // sin poly (odd, degree 9)
    float sp = fmaf(t, 2.75573188e-6f, -1.98408351e-4f);
    sp = fmaf(sp, t, 8.33333376e-3f);
    sp = fmaf(sp, t, -1.66666672e-1f);
    sp = fmaf(sp * t, r, r);
    // cos poly (even, degree 10)
    float cp = fmaf(t, -2.75573141e-7f, 2.47598227e-5f);
    cp = fmaf(cp, t, -1.38888894e-3f);
    cp = fmaf(cp, t, 4.16666679e-2f);
    cp = fmaf(cp, t, -5.00000000e-1f);
    cp = fmaf(cp, t, 1.0f);

    const float ss = (q & 1) ? cp : sp;
    const float cs = (q & 1) ? sp : cp;
    s_out = (q & 2)         ? -ss : ss;
    c_out = ((q + 1) & 2)   ? -cs : cs;
}

__global__ __launch_bounds__(TPB)
void rope_kernel(const float4* __restrict__ X, float4* __restrict__ O)
{
    const int d  = blockIdx.x * TPB + threadIdx.x;   // 0 .. HALF-1
    const int l0 = blockIdx.y * LPER;

    // e = d/2048 exact; theta = 10000^e correctly rounded to fp32 via double.
    const float  e      = (float)d * (1.0f / 2048.0f);
    const double log2c  = 13.2877123795494493915;    // log2(10000), double-rounded
    const float  theta  = (float)exp2((double)e * log2c);

    #pragma unroll
    for (int j = 0; j < LPER; ++j) {
        const int   l   = l0 + j;
        const float pos = (float)(l + 1);            // exact
        const float ang = __fmul_rn(pos, theta);     // matches reference rounding

        float s, c;
        sincos_of_f32(ang, s, c);

        const size_t base = (size_t)l * D + d;       // float4 index
        const float4 x1 = X[base];
        const float4 x2 = X[base + HALF];

        float4 o1, o2;
        o1.x = __fsub_rn(__fmul_rn(c, x1.x), __fmul_rn(s, x2.x));
        o1.y = __fsub_rn(__fmul_rn(c, x1.y), __fmul_rn(s, x2.y));
        o1.z = __fsub_rn(__fmul_rn(c, x1.z), __fmul_rn(s, x2.z));
        o1.w = __fsub_rn(__fmul_rn(c, x1.w), __fmul_rn(s, x2.w));

        o2.x = __fadd_rn(__fmul_rn(s, x1.x), __fmul_rn(c, x2.x));
        o2.y = __fadd_rn(__fmul_rn(s, x1.y), __fmul_rn(c, x2.y));
        o2.z = __fadd_rn(__fmul_rn(s, x1.z), __fmul_rn(c, x2.z));
        o2.w = __fadd_rn(__fmul_rn(s, x1.w), __fmul_rn(c, x2.w));

        O[base]        = o1;
        O[base + HALF] = o2;
    }
}

extern "C" void kernel_launch(void* const* d_in, const int* in_sizes, int n_in,
                              void* d_out, int out_size)
{
    (void)in_sizes; (void)n_in; (void)out_size;
    const float4* X = (const float4*)d_in[0];
    float4*       O = (float4*)d_out;

    dim3 grid(HALF / TPB, L / LPER);   // (8, 256)
    rope_kernel<<<grid, TPB>>>(X, O);
}

// round 3
// speedup vs baseline: 1.6857x; 1.6857x over previous
#include <cuda_runtime.h>

// RoPE: X (L=2048, D=4096, N=4) fp32 -> out same shape.
// ang[l,d] = round_f32((l+1) * theta_d), theta_d = 10000^(d/2048), ang up to 2e7.
// R2 post-mortem: fp64 Cody-Waite in the hot loop made the kernel
// FP64-throughput-bound (82us vs ~40us memory floor). This version moves all
// fp64 into a tiny per-d setup kernel and runs the per-angle reduction in
// pure fp32 using precomputed (theta mod pi/2) as a float-float pair.

constexpr int L    = 2048;
constexpr int D    = 4096;   // feature dim, indexed in float4 units over N=4
constexpr int HALF = 2048;
constexpr int LPER = 8;
constexpr int TPB  = 256;

// Per-d table: {theta, t_hi, t_lo, m&3 (as int bits)} where
// theta = m*(pi/2) + (t_hi + t_lo), decomposition exact to ~2e-16.
__device__ float4 g_tab[HALF];

__global__ void setup_kernel()
{
    const int d = blockIdx.x * blockDim.x + threadIdx.x;
    if (d >= HALF) return;

    // Bit-critical: identical theta expression to the passing R2 kernel.
    const float  e  = (float)d * (1.0f / 2048.0f);
    const double x  = (double)e * 13.2877123795494493915;   // log2(10000)
    const float  theta = (float)exp2(x);

    const double th = (double)theta;
    const double m  = floor(th * 0.63661977236758134308);   // 2/pi
    double t = fma(-m, 1.57079632679489661923, th);         // pi/2 hi
    t        = fma(-m, 6.12323399573676603587e-17, t);      // pi/2 lo
    const float t_hi = (float)t;
    const float t_lo = (float)(t - (double)t_hi);
    const int   m4   = ((long long)m) & 3;

    g_tab[d] = make_float4(theta, t_hi, t_lo, __int_as_float(m4));
}

__global__ __launch_bounds__(TPB)
void rope_kernel(const float4* __restrict__ X, float4* __restrict__ O)
{
    const int d  = blockIdx.x * TPB + threadIdx.x;   // 0 .. HALF-1
    const int l0 = blockIdx.y * LPER;

    const float4 tab  = g_tab[d];
    const float theta = tab.x;
    const float t_hi  = tab.y;
    const float t_lo  = tab.z;
    const int   m4    = __float_as_int(tab.w);

    #pragma unroll
    for (int j = 0; j < LPER; ++j) {
        const int   l     = l0 + j;
        const int   pos_i = l + 1;
        const float pos   = (float)pos_i;                 // exact (<= 2^11)

        // Reference's angle: single-rounded fp32 product, plus its exact residual.
        const float ang   = __fmul_rn(pos, theta);
        const float e_res = __fmaf_rn(pos, theta, -ang);  // exact: <=12-bit pos

        // u = pos * t as float-float (t = theta mod pi/2)
        const float u_hi = __fmul_rn(pos, t_hi);
        const float u_lo = __fmaf_rn(pos, t_lo, __fmaf_rn(pos, t_hi, -u_hi));

        // First reduction: k <= 2048, 2-term fp32 Cody-Waite (err ~1e-7)
        const float kf = rintf(u_hi * 0.63661977f);
        float r = __fmaf_rn(-kf, 1.57079637f,    u_hi);
        r       = __fmaf_rn(-kf, -4.37113883e-8f, r);

        // Fold in product-rounding residual (|e_res| <= 1) and u_lo
        float rt = (r - e_res) + u_lo;

        // Second reduction: k2 in {-1,0,1}
        const float k2f = rintf(rt * 0.63661977f);
        rt = __fmaf_rn(-k2f, 1.57079637f,    rt);
        rt = __fmaf_rn(-k2f, -4.37113883e-8f, rt);

        const int q = ((pos_i & 3) * m4 + (int)kf + (int)k2f) & 3;

        // Polynomials on |rt| <~ pi/4
        const float t2 = rt * rt;
        float sp = fmaf(t2, 2.75573188e-6f, -1.98408351e-4f);
        sp = fmaf(sp, t2, 8.33333376e-3f);
        sp = fmaf(sp, t2, -1.66666672e-1f);
        sp = fmaf(sp * t2, rt, rt);
        float cp = fmaf(t2, -2.75573141e-7f, 2.47598227e-5f);
        cp = fmaf(cp, t2, -1.38888894e-3f);
        cp = fmaf(cp, t2, 4.16666679e-2f);
        cp = fmaf(cp, t2, -5.00000000e-1f);
        cp = fmaf(cp, t2, 1.0f);

        const float ss = (q & 1) ? cp : sp;
        const float cs = (q & 1) ? sp : cp;
        const float s  = (q & 2)       ? -ss : ss;
        const float c  = ((q + 1) & 2) ? -cs : cs;

        const size_t base = (size_t)l * D + d;            // float4 index
        const float4 x1 = __ldcs(&X[base]);
        const float4 x2 = __ldcs(&X[base + HALF]);

        float4 o1, o2;
        o1.x = __fsub_rn(__fmul_rn(c, x1.x), __fmul_rn(s, x2.x));
        o1.y = __fsub_rn(__fmul_rn(c, x1.y), __fmul_rn(s, x2.y));
        o1.z = __fsub_rn(__fmul_rn(c, x1.z), __fmul_rn(s, x2.z));
        o1.w = __fsub_rn(__fmul_rn(c, x1.w), __fmul_rn(s, x2.w));

        o2.x = __fadd_rn(__fmul_rn(s, x1.x), __fmul_rn(c, x2.x));
        o2.y = __fadd_rn(__fmul_rn(s, x1.y), __fmul_rn(c, x2.y));
        o2.z = __fadd_rn(__fmul_rn(s, x1.z), __fmul_rn(c, x2.z));
        o2.w = __fadd_rn(__fmul_rn(s, x1.w), __fmul_rn(c, x2.w));

        __stcs(&O[base],        o1);
        __stcs(&O[base + HALF], o2);
    }
}

extern "C" void kernel_launch(void* const* d_in, const int* in_sizes, int n_in,
                              void* d_out, int out_size)
{
    (void)in_sizes; (void)n_in; (void)out_size;
    const float4* X = (const float4*)d_in[0];
    float4*       O = (float4*)d_out;

    setup_kernel<<<64, 32>>>();                 // spreads fp64 over 64 SMs, ~1us
    dim3 grid(HALF / TPB, L / LPER);            // (8, 256)
    rope_kernel<<<grid, TPB>>>(X, O);
}

// round 4
// speedup vs baseline: 1.7243x; 1.0229x over previous
#include <cuda_runtime.h>
#include <cmath>
#include <cstring>

// RoPE: X (L=2048, D=4096, N=4) fp32 -> out same shape.
// ang[l,d] = fl32((l+1) * theta_d), theta_d = 10000^(d/2048), angles to ~2e7.
//
// R3 post-mortem: main kernel was long-scoreboard bound (DRAM 67.7%, issue
// 22.8%) -> batch all 16 LDG.128 per thread ahead of compute for ~32KB/SM in
// flight. Setup kernel (one exp2(double) latency chain + launch overhead,
// ~8us total) replaced by a host-computed table delivered via one captured
// 32KB H2D memcpy node; host code runs only during graph capture.

constexpr int L    = 2048;
constexpr int D    = 4096;   // feature dim in float4 units over N=4
constexpr int HALF = 2048;
constexpr int LPER = 8;
constexpr int TPB  = 256;

// Per-d table: {theta, t_hi, t_lo, m&3 (int bits)} with
// theta = m*(pi/2) + (t_hi + t_lo), decomposition exact to ~2e-16.
__device__ float4 g_tab[HALF];

__global__ __launch_bounds__(TPB, 2)
void rope_kernel(const float4* __restrict__ X, float4* __restrict__ O)
{
    const int d  = blockIdx.x * TPB + threadIdx.x;   // 0 .. HALF-1
    const int l0 = blockIdx.y * LPER;

    const float4 tab  = g_tab[d];
    const float theta = tab.x;
    const float t_hi  = tab.y;
    const float t_lo  = tab.z;
    const int   m4    = __float_as_int(tab.w);

    const size_t base0 = (size_t)l0 * D + d;         // float4 index

    // Phase 1: issue all 16 wide loads (deep MLP; hides DRAM latency)
    float4 x1[LPER], x2[LPER];
    #pragma unroll
    for (int j = 0; j < LPER; ++j) {
        const size_t base = base0 + (size_t)j * D;
        x1[j] = __ldcs(&X[base]);
        x2[j] = __ldcs(&X[base + HALF]);
    }

    // Phase 2: trig + rotate + store
    #pragma unroll
    for (int j = 0; j < LPER; ++j) {
        const int   pos_i = l0 + j + 1;
        const float pos   = (float)pos_i;                 // exact (<= 2^11)

        // Reference's angle: single-rounded fp32 product + exact residual.
        const float ang   = __fmul_rn(pos, theta);
        const float e_res = __fmaf_rn(pos, theta, -ang);  // exact: <=12-bit pos

        // u = pos * (theta mod pi/2) as float-float
        const float u_hi = __fmul_rn(pos, t_hi);
        const float u_lo = __fmaf_rn(pos, t_lo, __fmaf_rn(pos, t_hi, -u_hi));

        // First reduction: k <= 2048, 2-term fp32 Cody-Waite (err ~1e-7)
        const float kf = rintf(u_hi * 0.63661977f);
        float r = __fmaf_rn(-kf, 1.57079637f,    u_hi);
        r       = __fmaf_rn(-kf, -4.37113883e-8f, r);

        // Fold in product-rounding residual (|e_res| <= 1) and u_lo
        float rt = (r - e_res) + u_lo;

        // Second reduction: k2 in {-1,0,1}
        const float k2f = rintf(rt * 0.63661977f);
        rt = __fmaf_rn(-k2f, 1.57079637f,    rt);
        rt = __fmaf_rn(-k2f, -4.37113883e-8f, rt);

        const int q = ((pos_i & 3) * m4 + (int)kf + (int)k2f) & 3;

        // Polynomials on |rt| <~ pi/4
        const float t2 = rt * rt;
        float sp = fmaf(t2, 2.75573188e-6f, -1.98408351e-4f);
        sp = fmaf(sp, t2, 8.33333376e-3f);
        sp = fmaf(sp, t2, -1.66666672e-1f);
        sp = fmaf(sp * t2, rt, rt);
        float cp = fmaf(t2, -2.75573141e-7f, 2.47598227e-5f);
        cp = fmaf(cp, t2, -1.38888894e-3f);
        cp = fmaf(cp, t2, 4.16666679e-2f);
        cp = fmaf(cp, t2, -5.00000000e-1f);
        cp = fmaf(cp, t2, 1.0f);

        const float ss = (q & 1) ? cp : sp;
        const float cs = (q & 1) ? sp : cp;
        const float s  = (q & 2)       ? -ss : ss;
        const float c  = ((q + 1) & 2) ? -cs : cs;

        float4 o1, o2;
        o1.x = __fsub_rn(__fmul_rn(c, x1[j].x), __fmul_rn(s, x2[j].x));
        o1.y = __fsub_rn(__fmul_rn(c, x1[j].y), __fmul_rn(s, x2[j].y));
        o1.z = __fsub_rn(__fmul_rn(c, x1[j].z), __fmul_rn(s, x2[j].z));
        o1.w = __fsub_rn(__fmul_rn(c, x1[j].w), __fmul_rn(s, x2[j].w));

        o2.x = __fadd_rn(__fmul_rn(s, x1[j].x), __fmul_rn(c, x2[j].x));
        o2.y = __fadd_rn(__fmul_rn(s, x1[j].y), __fmul_rn(c, x2[j].y));
        o2.z = __fadd_rn(__fmul_rn(s, x1[j].z), __fmul_rn(c, x2[j].z));
        o2.w = __fadd_rn(__fmul_rn(s, x1[j].w), __fmul_rn(c, x2[j].w));

        const size_t base = base0 + (size_t)j * D;
        __stcs(&O[base],        o1);
        __stcs(&O[base + HALF], o2);
    }
}

static float4 h_tab[HALF];   // persists across graph replays; filled every call

static void fill_table()
{
    for (int d = 0; d < HALF; ++d) {
        // Bit-critical path, same arithmetic as the passing R2/R3 kernels.
        const float  e  = (float)d * (1.0f / 2048.0f);
        const double x  = (double)e * 13.2877123795494493915;   // log2(10000)
        const float  theta = (float)std::exp2(x);

        const double th = (double)theta;
        const double m  = std::floor(th * 0.63661977236758134308); // 2/pi
        double t = std::fma(-m, 1.57079632679489661923, th);       // pi/2 hi
        t        = std::fma(-m, 6.12323399573676603587e-17, t);    // pi/2 lo
        const float t_hi = (float)t;
        const float t_lo = (float)(t - (double)t_hi);
        const int   m4   = (int)(((long long)m) & 3);

        float m4f;
        std::memcpy(&m4f, &m4, sizeof(float));
        h_tab[d] = make_float4(theta, t_hi, t_lo, m4f);
    }
}

extern "C" void kernel_launch(void* const* d_in, const int* in_sizes, int n_in,
                              void* d_out, int out_size)
{
    (void)in_sizes; (void)n_in; (void)out_size;
    const float4* X = (const float4*)d_in[0];
    float4*       O = (float4*)d_out;

    fill_table();   // host-only; runs during capture, not during replays

    cudaMemcpyToSymbolAsync(g_tab, h_tab, sizeof(h_tab), 0,
                            cudaMemcpyHostToDevice, 0);

    dim3 grid(HALF / TPB, L / LPER);            // (8, 256)
    rope_kernel<<<grid, TPB>>>(X, O);
}

// round 5
// speedup vs baseline: 1.8301x; 1.0614x over previous
#include <cuda_runtime.h>

// RoPE: X (L=2048, D=4096, N=4) fp32 -> out same shape.
// ang[l,d] = fl32((l+1) * theta_d), theta_d = 10000^(d/2048), angles to ~2e7.
//
// R4 post-mortem: captured pageable-H2D memcpy node cost ~11us (23% of
// runtime). The per-d table is a pure function of literals -> evaluate it at
// COMPILE TIME (constexpr double exp2 via Taylor + Dekker-split pi/2
// reduction) and bake it into a __device__ const array. Graph = 1 kernel node.

constexpr int L    = 2048;
constexpr int D    = 4096;   // feature dim in float4 units over N=4
constexpr int HALF = 2048;
constexpr int LPER = 8;
constexpr int TPB  = 256;

// ---------------- compile-time table generation ----------------

struct alignas(16) Entry { float theta, t_hi, t_lo; int m4; };
struct Table { Entry e[HALF]; };

// exp2(x), x in [0, 13.3), rel err ~5e-16 (compile-time IEEE doubles).
constexpr double cexp2(double x)
{
    const int    n = (int)(x + 0.5);
    const double f = x - (double)n;                  // [-0.5, 0.5], exact
    const double w = f * 0.69314718055994530942;     // f * ln2, |w| <= 0.347
    double p = 1.0;
    for (int k = 16; k >= 1; --k)                    // exp(w) Taylor, Horner
        p = 1.0 + p * w / (double)k;
    double s = 1.0;
    for (int i = 0; i < n; ++i) s *= 2.0;            // exact 2^n
    return s * p;                                    // exact scaling
}

constexpr Table make_table()
{
    Table T{};
    const double LOG2C   = 13.2877123795494493915;       // log2(10000)
    const double INVPIO2 = 0.63661977236758134308;       // 2/pi
    const double PIO2    = 1.57079632679489661923;       // double(pi/2)
    const double PIO2LO  = 6.12323399573676603587e-17;   // pi/2 - PIO2
    // Dekker split of PIO2: hi has <=26 bits -> m*hi exact for m < 2^24
    const double C   = 134217729.0 * PIO2;               // 2^27+1 splitter
    const double phi = C - (C - PIO2);
    const double plo = PIO2 - phi;

    for (int d = 0; d < HALF; ++d) {
        const float  e  = (float)d * (1.0f / 2048.0f);   // exact
        const double x  = (double)e * LOG2C;             // same rounding as ref
        const float  th = (float)cexp2(x);

        const double thd = (double)th;
        const long long mi = (long long)(thd * INVPIO2); // floor (positive)
        const double m = (double)mi;

        double t = thd - m * phi;    // m*phi exact; Sterbenz-exact subtraction
        t -= m * plo;                // m*plo exact; one rounding ~1e-16
        t -= m * PIO2LO;             // tiny correction

        T.e[d].theta = th;
        T.e[d].t_hi  = (float)t;
        T.e[d].t_lo  = (float)(t - (double)T.e[d].t_hi);
        T.e[d].m4    = (int)(mi & 3);
    }
    return T;
}

__device__ constexpr Table g_tab = make_table();

// ---------------- main kernel (unchanged structure from R4) ----------------

__global__ __launch_bounds__(TPB, 2)
void rope_kernel(const float4* __restrict__ X, float4* __restrict__ O)
{
    const int d  = blockIdx.x * TPB + threadIdx.x;   // 0 .. HALF-1
    const int l0 = blockIdx.y * LPER;

    const float4 tab  = reinterpret_cast<const float4*>(g_tab.e)[d];
    const float theta = tab.x;
    const float t_hi  = tab.y;
    const float t_lo  = tab.z;
    const int   m4    = __float_as_int(tab.w);

    const size_t base0 = (size_t)l0 * D + d;         // float4 index

    // Phase 1: issue all 16 wide loads (deep MLP; hides DRAM latency)
    float4 x1[LPER], x2[LPER];
    #pragma unroll
    for (int j = 0; j < LPER; ++j) {
        const size_t base = base0 + (size_t)j * D;
        x1[j] = __ldcs(&X[base]);
        x2[j] = __ldcs(&X[base + HALF]);
    }

    // Phase 2: trig + rotate + store
    #pragma unroll
    for (int j = 0; j < LPER; ++j) {
        const int   pos_i = l0 + j + 1;
        const float pos   = (float)pos_i;                 // exact (<= 2^11)

        // Reference's angle: single-rounded fp32 product + exact residual.
        const float ang   = __fmul_rn(pos, theta);
        const float e_res = __fmaf_rn(pos, theta, -ang);  // exact: <=12-bit pos

        // u = pos * (theta mod pi/2) as float-float
        const float u_hi = __fmul_rn(pos, t_hi);
        const float u_lo = __fmaf_rn(pos, t_lo, __fmaf_rn(pos, t_hi, -u_hi));

        // First reduction: k <= 2048, 2-term fp32 Cody-Waite (err ~1e-7)
        const float kf = rintf(u_hi * 0.63661977f);
        float r = __fmaf_rn(-kf, 1.57079637f,    u_hi);
        r       = __fmaf_rn(-kf, -4.37113883e-8f, r);

        // Fold in product-rounding residual (|e_res| <= 1) and u_lo
        float rt = (r - e_res) + u_lo;

        // Second reduction: k2 in {-1,0,1}
        const float k2f = rintf(rt * 0.63661977f);
        rt = __fmaf_rn(-k2f, 1.57079637f,    rt);
        rt = __fmaf_rn(-k2f, -4.37113883e-8f, rt);

        const int q = ((pos_i & 3) * m4 + (int)kf + (int)k2f) & 3;

        // Polynomials on |rt| <~ pi/4
        const float t2 = rt * rt;
        float sp = fmaf(t2, 2.75573188e-6f, -1.98408351e-4f);
        sp = fmaf(sp, t2, 8.33333376e-3f);
        sp = fmaf(sp, t2, -1.66666672e-1f);
        sp = fmaf(sp * t2, rt, rt);
        float cp = fmaf(t2, -2.75573141e-7f, 2.47598227e-5f);
        cp = fmaf(cp, t2, -1.38888894e-3f);
        cp = fmaf(cp, t2, 4.16666679e-2f);
        cp = fmaf(cp, t2, -5.00000000e-1f);
        cp = fmaf(cp, t2, 1.0f);

        const float ss = (q & 1) ? cp : sp;
        const float cs = (q & 1) ? sp : cp;
        const float s  = (q & 2)       ? -ss : ss;
        const float c  = ((q + 1) & 2) ? -cs : cs;

        float4 o1, o2;
        o1.x = __fsub_rn(__fmul_rn(c, x1[j].x), __fmul_rn(s, x2[j].x));
        o1.y = __fsub_rn(__fmul_rn(c, x1[j].y), __fmul_rn(s, x2[j].y));
        o1.z = __fsub_rn(__fmul_rn(c, x1[j].z), __fmul_rn(s, x2[j].z));
        o1.w = __fsub_rn(__fmul_rn(c, x1[j].w), __fmul_rn(s, x2[j].w));

        o2.x = __fadd_rn(__fmul_rn(s, x1[j].x), __fmul_rn(c, x2[j].x));
        o2.y = __fadd_rn(__fmul_rn(s, x1[j].y), __fmul_rn(c, x2[j].y));
        o2.z = __fadd_rn(__fmul_rn(s, x1[j].z), __fmul_rn(c, x2[j].z));
        o2.w = __fadd_rn(__fmul_rn(s, x1[j].w), __fmul_rn(c, x2[j].w));

        const size_t base = base0 + (size_t)j * D;
        __stcs(&O[base],        o1);
        __stcs(&O[base + HALF], o2);
    }
}

extern "C" void kernel_launch(void* const* d_in, const int* in_sizes, int n_in,
                              void* d_out, int out_size)
{
    (void)in_sizes; (void)n_in; (void)out_size;
    const float4* X = (const float4*)d_in[0];
    float4*       O = (float4*)d_out;

    dim3 grid(HALF / TPB, L / LPER);            // (8, 256)
    rope_kernel<<<grid, TPB>>>(X, O);
}

// round 6
// speedup vs baseline: 1.8743x; 1.0241x over previous
#include <cuda_runtime.h>

// RoPE: X (L=2048, D=4096, N=4) fp32 -> out same shape.
// ang[l,d] = fl32((l+1) * theta_d), theta_d = 10000^(d/2048), angles to ~2e7.
//
// R5 post-mortem: kernel at DRAM 70%, occ 20.3% (regs=126 -> 2 CTAs/SM).
// Warp supply, not per-thread MLP, limits bandwidth. This round: LPER 8->4
// with __launch_bounds__(256,4) -> <=64 regs, 4 CTAs/SM, 2x warps, finer
// wave granularity. Bit-critical math unchanged.

constexpr int L    = 2048;
constexpr int D    = 4096;   // feature dim in float4 units over N=4
constexpr int HALF = 2048;
constexpr int LPER = 4;
constexpr int TPB  = 256;

// ---------------- compile-time table generation ----------------

struct alignas(16) Entry { float theta, t_hi, t_lo; int m4; };
struct Table { Entry e[HALF]; };

// exp2(x), x in [0, 13.3), rel err ~5e-16 (compile-time IEEE doubles).
constexpr double cexp2(double x)
{
    const int    n = (int)(x + 0.5);
    const double f = x - (double)n;                  // [-0.5, 0.5], exact
    const double w = f * 0.69314718055994530942;     // f * ln2, |w| <= 0.347
    double p = 1.0;
    for (int k = 16; k >= 1; --k)                    // exp(w) Taylor, Horner
        p = 1.0 + p * w / (double)k;
    double s = 1.0;
    for (int i = 0; i < n; ++i) s *= 2.0;            // exact 2^n
    return s * p;                                    // exact scaling
}

constexpr Table make_table()
{
    Table T{};
    const double LOG2C   = 13.2877123795494493915;       // log2(10000)
    const double INVPIO2 = 0.63661977236758134308;       // 2/pi
    const double PIO2    = 1.57079632679489661923;       // double(pi/2)
    const double PIO2LO  = 6.12323399573676603587e-17;   // pi/2 - PIO2
    // Dekker split of PIO2: hi has <=26 bits -> m*hi exact for m < 2^24
    const double C   = 134217729.0 * PIO2;               // 2^27+1 splitter
    const double phi = C - (C - PIO2);
    const double plo = PIO2 - phi;

    for (int d = 0; d < HALF; ++d) {
        const float  e  = (float)d * (1.0f / 2048.0f);   // exact
        const double x  = (double)e * LOG2C;             // same rounding as ref
        const float  th = (float)cexp2(x);

        const double thd = (double)th;
        const long long mi = (long long)(thd * INVPIO2); // floor (positive)
        const double m = (double)mi;

        double t = thd - m * phi;    // m*phi exact; Sterbenz-exact subtraction
        t -= m * plo;                // m*plo exact; one rounding ~1e-16
        t -= m * PIO2LO;             // tiny correction

        T.e[d].theta = th;
        T.e[d].t_hi  = (float)t;
        T.e[d].t_lo  = (float)(t - (double)T.e[d].t_hi);
        T.e[d].m4    = (int)(mi & 3);
    }
    return T;
}

__device__ constexpr Table g_tab = make_table();

// ---------------- main kernel ----------------

__global__ __launch_bounds__(TPB, 4)
void rope_kernel(const float4* __restrict__ X, float4* __restrict__ O)
{
    const int d  = blockIdx.x * TPB + threadIdx.x;   // 0 .. HALF-1
    const int l0 = blockIdx.y * LPER;

    const float4 tab  = reinterpret_cast<const float4*>(g_tab.e)[d];
    const float theta = tab.x;
    const float t_hi  = tab.y;
    const float t_lo  = tab.z;
    const int   m4    = __float_as_int(tab.w);

    const size_t base0 = (size_t)l0 * D + d;         // float4 index

    // Phase 1: issue all 8 wide loads (deep MLP; hides DRAM latency)
    float4 x1[LPER], x2[LPER];
    #pragma unroll
    for (int j = 0; j < LPER; ++j) {
        const size_t base = base0 + (size_t)j * D;
        x1[j] = __ldcs(&X[base]);
        x2[j] = __ldcs(&X[base + HALF]);
    }

    // Phase 2: trig + rotate + store
    #pragma unroll
    for (int j = 0; j < LPER; ++j) {
        const int   pos_i = l0 + j + 1;
        const float pos   = (float)pos_i;                 // exact (<= 2^11)

        // Reference's angle: single-rounded fp32 product + exact residual.
        const float ang   = __fmul_rn(pos, theta);
        const float e_res = __fmaf_rn(pos, theta, -ang);  // exact: <=12-bit pos

        // u = pos * (theta mod pi/2) as float-float
        const float u_hi = __fmul_rn(pos, t_hi);
        const float u_lo = __fmaf_rn(pos, t_lo, __fmaf_rn(pos, t_hi, -u_hi));

        // First reduction: k <= 2048, 2-term fp32 Cody-Waite (err ~1e-7)
        const float kf = rintf(u_hi * 0.63661977f);
        float r = __fmaf_rn(-kf, 1.57079637f,    u_hi);
        r       = __fmaf_rn(-kf, -4.37113883e-8f, r);

        // Fold in product-rounding residual (|e_res| <= 1) and u_lo
        float rt = (r - e_res) + u_lo;

        // Second reduction: k2 in {-1,0,1}
        const float k2f = rintf(rt * 0.63661977f);
        rt = __fmaf_rn(-k2f, 1.57079637f,    rt);
        rt = __fmaf_rn(-k2f, -4.37113883e-8f, rt);

        const int q = ((pos_i & 3) * m4 + (int)kf + (int)k2f) & 3;

        // Polynomials on |rt| <~ pi/4
        const float t2 = rt * rt;
        float sp = fmaf(t2, 2.75573188e-6f, -1.98408351e-4f);
        sp = fmaf(sp, t2, 8.33333376e-3f);
        sp = fmaf(sp, t2, -1.66666672e-1f);
        sp = fmaf(sp * t2, rt, rt);
        float cp = fmaf(t2, -2.75573141e-7f, 2.47598227e-5f);
        cp = fmaf(cp, t2, -1.38888894e-3f);
        cp = fmaf(cp, t2, 4.16666679e-2f);
        cp = fmaf(cp, t2, -5.00000000e-1f);
        cp = fmaf(cp, t2, 1.0f);

        const float ss = (q & 1) ? cp : sp;
        const float cs = (q & 1) ? sp : cp;
        const float s  = (q & 2)       ? -ss : ss;
        const float c  = ((q + 1) & 2) ? -cs : cs;

        float4 o1, o2;
        o1.x = __fsub_rn(__fmul_rn(c, x1[j].x), __fmul_rn(s, x2[j].x));
        o1.y = __fsub_rn(__fmul_rn(c, x1[j].y), __fmul_rn(s, x2[j].y));
        o1.z = __fsub_rn(__fmul_rn(c, x1[j].z), __fmul_rn(s, x2[j].z));
        o1.w = __fsub_rn(__fmul_rn(c, x1[j].w), __fmul_rn(s, x2[j].w));

        o2.x = __fadd_rn(__fmul_rn(s, x1[j].x), __fmul_rn(c, x2[j].x));
        o2.y = __fadd_rn(__fmul_rn(s, x1[j].y), __fmul_rn(c, x2[j].y));
        o2.z = __fadd_rn(__fmul_rn(s, x1[j].z), __fmul_rn(c, x2[j].z));
        o2.w = __fadd_rn(__fmul_rn(s, x1[j].w), __fmul_rn(c, x2[j].w));

        const size_t base = base0 + (size_t)j * D;
        __stcs(&O[base],        o1);
        __stcs(&O[base + HALF], o2);
    }
}

extern "C" void kernel_launch(void* const* d_in, const int* in_sizes, int n_in,
                              void* d_out, int out_size)
{
    (void)in_sizes; (void)n_in; (void)out_size;
    const float4* X = (const float4*)d_in[0];
    float4*       O = (float4*)d_out;

    dim3 grid(HALF / TPB, L / LPER);            // (8, 512)
    rope_kernel<<<grid, TPB>>>(X, O);
}